// round 4
// baseline (speedup 1.0000x reference)
#include <cuda_runtime.h>
#include <cstdint>

// Problem constants
#define BATCH   2048
#define TSTEPS  250
#define DIN     128
#define HID     100
#define G4      400          // 4*HID
#define MTOT    (BATCH*TSTEPS)   // 512000 rows of x / xz

// Scratch for xz = x@Wi + bh : [B*T, 400] fp32 (819.2 MB, static device alloc)
__device__ float g_xz[(size_t)MTOT * G4];

// ---------------------------------------------------------------------------
// Kernel 1: xz[m][n] = sum_k x[m][k] * Wi[k][n] + bh[n]
// M = 512000, K = 128 (fully resident), N = 400. Tiles: BM=64, BN=80.
// 256 threads, 4x5 register microtile per thread.
// ---------------------------------------------------------------------------
__global__ __launch_bounds__(256) void gemm_xz_kernel(
    const float* __restrict__ x,
    const float* __restrict__ Wi,
    const float* __restrict__ bh)
{
    extern __shared__ float sm1[];
    float* xs = sm1;              // [64][128]
    float* ws = sm1 + 64 * 128;   // [128][80]

    const int m0  = blockIdx.x * 64;
    const int n0  = blockIdx.y * 80;
    const int tid = threadIdx.x;

    // Load x tile (coalesced float4): 64*128 floats = 2048 float4
    {
        const float4* xg  = (const float4*)(x + (size_t)m0 * DIN);
        float4*       xs4 = (float4*)xs;
#pragma unroll
        for (int i = 0; i < 8; i++) xs4[tid + 256 * i] = xg[tid + 256 * i];
    }
    // Load Wi tile: 128 x 80
    for (int i = tid; i < 128 * 80; i += 256) {
        int k = i / 80, c = i - k * 80;
        ws[i] = Wi[k * G4 + n0 + c];
    }
    __syncthreads();

    const int tx = tid & 15;       // column group 0..15
    const int ty = tid >> 4;       // row group 0..15

    float acc[4][5];
#pragma unroll
    for (int i = 0; i < 4; i++)
#pragma unroll
        for (int j = 0; j < 5; j++) acc[i][j] = 0.f;

#pragma unroll 4
    for (int k = 0; k < 128; k++) {
        float a[4], b[5];
#pragma unroll
        for (int i = 0; i < 4; i++) a[i] = xs[(ty + 16 * i) * 128 + k];
#pragma unroll
        for (int j = 0; j < 5; j++) b[j] = ws[k * 80 + tx + 16 * j];
#pragma unroll
        for (int i = 0; i < 4; i++)
#pragma unroll
            for (int j = 0; j < 5; j++) acc[i][j] += a[i] * b[j];
    }

#pragma unroll
    for (int i = 0; i < 4; i++) {
        const size_t m = (size_t)(m0 + ty + 16 * i);
#pragma unroll
        for (int j = 0; j < 5; j++) {
            const int n = n0 + tx + 16 * j;
            g_xz[m * G4 + n] = acc[i][j] + bh[n];
        }
    }
}

// ---------------------------------------------------------------------------
// Kernel 2: persistent LSTM recurrence + fused output projection.
// 128 CTAs, each owns 16 batch rows for all 250 timesteps.
// blockDim = 400: thread t -> j = t%100 (hidden column), rg = t/100 (row group),
// handling rows rg, rg+4, rg+8, rg+12 and all 4 gates for hidden unit j.
// Smem: Wh[100][400] + Wd[100][100] + h[16][100] + bd[100] = 206,800 B.
// c stays in registers (thread owns h[r][j]/c[r][j] for its 4 rows).
// ---------------------------------------------------------------------------
__device__ __forceinline__ float sigf(float xv) {
    return __fdividef(1.f, 1.f + __expf(-xv));
}
__device__ __forceinline__ float tanh_f(float xv) {
    float e = __expf(2.f * xv);
    return 1.f - __fdividef(2.f, e + 1.f);
}

__global__ __launch_bounds__(400) void lstm_kernel(
    const float* __restrict__ Wh,
    const float* __restrict__ Wd,
    const float* __restrict__ bd,
    float* __restrict__ out)
{
    extern __shared__ float sm2[];
    float* Whs = sm2;                   // [100][400]
    float* Wds = Whs + HID * G4;        // [100][100]
    float* hsh = Wds + HID * HID;       // [16][100]
    float* bds = hsh + 16 * HID;        // [100]

    const int tid = threadIdx.x;        // 0..399
    for (int i = tid; i < HID * G4; i += 400) Whs[i] = Wh[i];
    for (int i = tid; i < HID * HID; i += 400) Wds[i] = Wd[i];
    for (int i = tid; i < 16 * HID; i += 400) hsh[i] = 0.f;
    if (tid < HID) bds[tid] = bd[tid];
    __syncthreads();

    const int j  = tid % HID;           // hidden column
    const int rg = tid / HID;           // row group 0..3
    const int r0 = blockIdx.x * 16;     // first batch row of this CTA

    float cst[4] = {0.f, 0.f, 0.f, 0.f};

    // Software-prefetched xz registers: 4 rows x 4 gates
    float xzc[16], xzn[16];
#pragma unroll
    for (int i = 0; i < 4; i++) {
        const size_t base = ((size_t)(r0 + rg + 4 * i) * TSTEPS + 0) * G4;
#pragma unroll
        for (int g = 0; g < 4; g++) xzc[i * 4 + g] = g_xz[base + g * HID + j];
    }

    for (int t = 0; t < TSTEPS; t++) {
        // Prefetch next timestep's xz (latency hidden under the dot loop)
        if (t < TSTEPS - 1) {
#pragma unroll
            for (int i = 0; i < 4; i++) {
                const size_t base =
                    ((size_t)(r0 + rg + 4 * i) * TSTEPS + (t + 1)) * G4;
#pragma unroll
                for (int g = 0; g < 4; g++)
                    xzn[i * 4 + g] = g_xz[base + g * HID + j];
            }
        }

        // z[r][g*100+j] = xz + sum_k h[r][k] * Wh[k][g*100+j]
        float acc[4][4];
#pragma unroll
        for (int i = 0; i < 4; i++)
#pragma unroll
            for (int g = 0; g < 4; g++) acc[i][g] = xzc[i * 4 + g];

#pragma unroll 2
        for (int k = 0; k < HID; k++) {
            float wv[4];
#pragma unroll
            for (int g = 0; g < 4; g++) wv[g] = Whs[k * G4 + g * HID + j];
#pragma unroll
            for (int i = 0; i < 4; i++) {
                const float hv = hsh[(rg + 4 * i) * HID + k];
#pragma unroll
                for (int g = 0; g < 4; g++) acc[i][g] += hv * wv[g];
            }
        }

        // Gates (flax order i, f, g, o), cell + hidden update
        float hnew[4];
#pragma unroll
        for (int i = 0; i < 4; i++) {
            const float ig = sigf(acc[i][0]);
            const float fg = sigf(acc[i][1]);
            const float gg = tanh_f(acc[i][2]);
            const float og = sigf(acc[i][3]);
            const float c  = fg * cst[i] + ig * gg;
            cst[i]  = c;
            hnew[i] = og * tanh_f(c);
        }

        __syncthreads();   // everyone done reading previous h (dot + prev proj)
#pragma unroll
        for (int i = 0; i < 4; i++) hsh[(rg + 4 * i) * HID + j] = hnew[i];
        __syncthreads();   // new h visible

        // Output projection: out[r][t][j] = relu(bd[j] + sum_k h[r][k]*Wd[k][j])
        float pv[4] = {0.f, 0.f, 0.f, 0.f};
#pragma unroll 2
        for (int k = 0; k < HID; k++) {
            const float wv = Wds[k * HID + j];
#pragma unroll
            for (int i = 0; i < 4; i++)
                pv[i] += hsh[(rg + 4 * i) * HID + k] * wv;
        }
#pragma unroll
        for (int i = 0; i < 4; i++) {
            const float v = pv[i] + bds[j];
            const size_t o =
                ((size_t)(r0 + rg + 4 * i) * TSTEPS + t) * HID + j;
            out[o] = fmaxf(v, 0.f);
        }

#pragma unroll
        for (int q = 0; q < 16; q++) xzc[q] = xzn[q];
    }
}

// ---------------------------------------------------------------------------
// Launch
// ---------------------------------------------------------------------------
extern "C" void kernel_launch(void* const* d_in, const int* in_sizes, int n_in,
                              void* d_out, int out_size)
{
    const float* x  = (const float*)d_in[0];   // [2048,250,128]
    const float* Wi = (const float*)d_in[1];   // [128,400]
    const float* Wh = (const float*)d_in[2];   // [100,400]
    const float* bh = (const float*)d_in[3];   // [400]
    const float* Wd = (const float*)d_in[4];   // [100,100]
    const float* bd = (const float*)d_in[5];   // [100]
    float* out = (float*)d_out;                // [2048,250,100]

    const int smem1 = (64 * 128 + 128 * 80) * 4;                       // 73,728 B
    const int smem2 = (HID * G4 + HID * HID + 16 * HID + HID) * 4;     // 206,800 B
    cudaFuncSetAttribute(gemm_xz_kernel,
                         cudaFuncAttributeMaxDynamicSharedMemorySize, smem1);
    cudaFuncSetAttribute(lstm_kernel,
                         cudaFuncAttributeMaxDynamicSharedMemorySize, smem2);

    dim3 g1(MTOT / 64, G4 / 80);   // 8000 x 5
    gemm_xz_kernel<<<g1, 256, smem1>>>(x, Wi, bh);
    lstm_kernel<<<BATCH / 16, 400, smem2>>>(Wh, Wd, bd, out);
}

// round 5
// speedup vs baseline: 1.2062x; 1.2062x over previous
#include <cuda_runtime.h>
#include <cstdint>

typedef unsigned long long ull;

#define BATCH   2048
#define TSTEPS  250
#define DIN     128
#define HID     100
#define G4      400
#define MTOT    (BATCH*TSTEPS)

// Scratch for xz = x@Wi + bh : [B*T, 400] fp32
__device__ float g_xz[(size_t)MTOT * G4];

// ---------------------------------------------------------------------------
// f32x2 packed-FMA helpers (sm_103a)
// ---------------------------------------------------------------------------
__device__ __forceinline__ uint32_t sptr(const void* p) {
    return (uint32_t)__cvta_generic_to_shared(p);
}
__device__ __forceinline__ void lds2(ull& a, ull& b, uint32_t addr) {
    asm volatile("ld.shared.v2.b64 {%0,%1}, [%2];" : "=l"(a), "=l"(b) : "r"(addr));
}
__device__ __forceinline__ ull lds1(uint32_t addr) {
    ull a; asm volatile("ld.shared.b64 %0, [%1];" : "=l"(a) : "r"(addr)); return a;
}
__device__ __forceinline__ void ffma2(ull& d, ull a, ull b) {
    asm volatile("fma.rn.f32x2 %0, %1, %2, %0;" : "+l"(d) : "l"(a), "l"(b));
}
__device__ __forceinline__ ull pack2(float lo, float hi) {
    ull r; asm("mov.b64 %0, {%1,%2};" : "=l"(r) : "f"(lo), "f"(hi)); return r;
}
__device__ __forceinline__ float hsum2(ull v) {
    float lo, hi; asm("mov.b64 {%0,%1}, %2;" : "=f"(lo), "=f"(hi) : "l"(v));
    return lo + hi;
}

// ---------------------------------------------------------------------------
// Kernel 1: xz = x@Wi + bh.  M=512000, K=128, N=400. BM=64, BN=80, 256 thr.
// K-paired f32x2: acc2 accumulates (even-k, odd-k) partial sums.
// Wi tile transposed in smem to [n][k] (pad 132) so b-pairs are k-contiguous.
// ---------------------------------------------------------------------------
#define PWS 132

__global__ __launch_bounds__(256, 2) void gemm_xz_kernel(
    const float* __restrict__ x,
    const float* __restrict__ Wi,
    const float* __restrict__ bh)
{
    extern __shared__ float sm1[];
    float* xs = sm1;                 // [64][128]  (natural, k contiguous)
    float* ws = sm1 + 64 * 128;      // [80][PWS]  (transposed, k contiguous)

    const int m0  = blockIdx.x * 64;
    const int n0  = blockIdx.y * 80;
    const int tid = threadIdx.x;

    {
        const float4* xg  = (const float4*)(x + (size_t)m0 * DIN);
        float4*       xs4 = (float4*)xs;
#pragma unroll
        for (int i = 0; i < 8; i++) xs4[tid + 256 * i] = xg[tid + 256 * i];
    }
    for (int i = tid; i < 128 * 80; i += 256) {
        int k = i / 80, c = i - k * 80;
        ws[c * PWS + k] = Wi[k * G4 + n0 + c];
    }
    __syncthreads();

    const int tx = tid & 15;   // column 0..15 (cols tx+16j)
    const int ty = tid >> 4;   // row 0..15    (rows ty+16i)

    ull acc[4][5];
#pragma unroll
    for (int i = 0; i < 4; i++)
#pragma unroll
        for (int jn = 0; jn < 5; jn++) acc[i][jn] = 0ull;

    const uint32_t xbase = sptr(xs) + ty * (128 * 4);
    const uint32_t wbase = sptr(ws) + tx * (PWS * 4);

#pragma unroll 8
    for (int k = 0; k < 128; k += 4) {
        ull a[4][2], b[5][2];
#pragma unroll
        for (int i = 0; i < 4; i++)
            lds2(a[i][0], a[i][1], xbase + i * (16 * 128 * 4) + k * 4);
#pragma unroll
        for (int jn = 0; jn < 5; jn++)
            lds2(b[jn][0], b[jn][1], wbase + jn * (16 * PWS * 4) + k * 4);
#pragma unroll
        for (int i = 0; i < 4; i++)
#pragma unroll
            for (int jn = 0; jn < 5; jn++) {
                ffma2(acc[i][jn], a[i][0], b[jn][0]);
                ffma2(acc[i][jn], a[i][1], b[jn][1]);
            }
    }

#pragma unroll
    for (int i = 0; i < 4; i++) {
        const size_t m = (size_t)(m0 + ty + 16 * i);
#pragma unroll
        for (int jn = 0; jn < 5; jn++) {
            const int n = n0 + tx + 16 * jn;
            g_xz[m * G4 + n] = hsum2(acc[i][jn]) + bh[n];
        }
    }
}

// ---------------------------------------------------------------------------
// Kernel 2: persistent LSTM recurrence + fused projection, f32x2 everywhere.
// 128 CTAs x 16 batch rows, 200 threads: thread = (j = tid%100, rr = tid/100),
// owns 8 contiguous rows (rr*8 .. rr*8+7) and hidden unit j (all 4 gates).
//
// Smem layouts (all k-contiguous for paired loads):
//   Wq [50 k2][2 gp][100 j] float4 = (g_{2gp}[2k2], g_{2gp}[2k2+1],
//                                     g_{2gp+1}[2k2], g_{2gp+1}[2k2+1])
//   Wdp[50 k2][100 j] float2 = (Wd[2k2][j], Wd[2k2+1][j])
//   h  [16][100] natural (LDS.128 gives 2 k-pairs, broadcast per warp)
// ---------------------------------------------------------------------------
__device__ __forceinline__ float sigf(float xv) {
    return __fdividef(1.f, 1.f + __expf(-xv));
}
__device__ __forceinline__ float tanh_f(float xv) {
    float e = __expf(2.f * xv);
    return 1.f - __fdividef(2.f, e + 1.f);
}

__global__ __launch_bounds__(200) void lstm_kernel(
    const float* __restrict__ Wh,
    const float* __restrict__ Wd,
    const float* __restrict__ bd,
    float* __restrict__ out)
{
    extern __shared__ float sm2[];
    float* Wq  = sm2;                 // 40000 floats
    float* Wdp = sm2 + 40000;         // 10000 floats
    float* hsm = sm2 + 50000;         // 1600 floats
    float* bds = sm2 + 51600;         // 100 floats

    const int tid = threadIdx.x;      // 0..199

    for (int i = tid; i < HID * G4; i += 200) {
        int k = i / G4, c = i - k * G4;
        int k2 = k >> 1, kl = k & 1;
        int g = c / HID, j = c - g * HID;
        int gp = g >> 1, gl = g & 1;
        Wq[(((k2 * 2 + gp) * HID + j) << 2) + gl * 2 + kl] = Wh[i];
    }
    for (int i = tid; i < HID * HID; i += 200) {
        int k = i / HID, j = i - k * HID;
        Wdp[(k >> 1) * (2 * HID) + j * 2 + (k & 1)] = Wd[i];
    }
    for (int i = tid; i < 16 * HID; i += 200) hsm[i] = 0.f;
    if (tid < HID) bds[tid] = bd[tid];
    __syncthreads();

    const int j  = tid % HID;
    const int rr = tid / HID;                     // 0..1
    const int r0 = blockIdx.x * 16 + rr * 8;      // first of 8 rows

    const uint32_t hrow = sptr(hsm) + (rr * 8) * (HID * 4);
    const uint32_t wqb  = sptr(Wq)  + j * 16;
    const uint32_t wdb  = sptr(Wdp) + j * 8;

    float cst[8];
#pragma unroll
    for (int i = 0; i < 8; i++) cst[i] = 0.f;

    // Prefetched xz for the current step: 8 rows x 4 gates
    float xzn[32];
#pragma unroll
    for (int i = 0; i < 8; i++) {
        const float* p = g_xz + ((size_t)(r0 + i) * TSTEPS) * G4 + j;
#pragma unroll
        for (int g = 0; g < 4; g++) xzn[i * 4 + g] = __ldcs(p + g * HID);
    }

    for (int t = 0; t < TSTEPS; t++) {
        // init accumulators from this step's xz, then prefetch next step
        ull acc[8][4];
#pragma unroll
        for (int i = 0; i < 8; i++)
#pragma unroll
            for (int g = 0; g < 4; g++) acc[i][g] = pack2(xzn[i * 4 + g], 0.f);

        if (t + 1 < TSTEPS) {
#pragma unroll
            for (int i = 0; i < 8; i++) {
                const float* p =
                    g_xz + ((size_t)(r0 + i) * TSTEPS + (t + 1)) * G4 + j;
#pragma unroll
                for (int g = 0; g < 4; g++) xzn[i * 4 + g] = __ldcs(p + g * HID);
            }
        }

        // recurrence: acc[i][g] += sum_k h[r][k] * Wh[k][g*100+j]  (k-paired)
#pragma unroll 5
        for (int k4 = 0; k4 < 25; k4++) {
            ull a[8][2];
#pragma unroll
            for (int i = 0; i < 8; i++)
                lds2(a[i][0], a[i][1], hrow + i * (HID * 4) + k4 * 16);
            ull bg[2][4];
#pragma unroll
            for (int kl = 0; kl < 2; kl++) {
                int k2 = 2 * k4 + kl;
                lds2(bg[kl][0], bg[kl][1], wqb + (k2 * 2 + 0) * (HID * 16));
                lds2(bg[kl][2], bg[kl][3], wqb + (k2 * 2 + 1) * (HID * 16));
            }
#pragma unroll
            for (int i = 0; i < 8; i++)
#pragma unroll
                for (int g = 0; g < 4; g++) {
                    ffma2(acc[i][g], a[i][0], bg[0][g]);
                    ffma2(acc[i][g], a[i][1], bg[1][g]);
                }
        }

        // gates (i, f, g, o), cell + hidden update
        float hnew[8];
#pragma unroll
        for (int i = 0; i < 8; i++) {
            const float ig = sigf(hsum2(acc[i][0]));
            const float fg = sigf(hsum2(acc[i][1]));
            const float gg = tanh_f(hsum2(acc[i][2]));
            const float og = sigf(hsum2(acc[i][3]));
            const float c  = fg * cst[i] + ig * gg;
            cst[i]  = c;
            hnew[i] = og * tanh_f(c);
        }

        __syncthreads();   // all rec reads of old h done
#pragma unroll
        for (int i = 0; i < 8; i++) hsm[(rr * 8 + i) * HID + j] = hnew[i];
        __syncthreads();   // new h visible

        // projection: out[r][t][j] = relu(bd[j] + sum_k h[r][k]*Wd[k][j])
        ull pv[8];
#pragma unroll
        for (int i = 0; i < 8; i++) pv[i] = 0ull;
#pragma unroll 5
        for (int k4 = 0; k4 < 25; k4++) {
            ull a[8][2];
#pragma unroll
            for (int i = 0; i < 8; i++)
                lds2(a[i][0], a[i][1], hrow + i * (HID * 4) + k4 * 16);
            const ull w0 = lds1(wdb + (2 * k4 + 0) * (HID * 8));
            const ull w1 = lds1(wdb + (2 * k4 + 1) * (HID * 8));
#pragma unroll
            for (int i = 0; i < 8; i++) {
                ffma2(pv[i], a[i][0], w0);
                ffma2(pv[i], a[i][1], w1);
            }
        }
        const float bj = bds[j];
#pragma unroll
        for (int i = 0; i < 8; i++) {
            const float v = hsum2(pv[i]) + bj;
            out[((size_t)(r0 + i) * TSTEPS + t) * HID + j] = fmaxf(v, 0.f);
        }
    }
}

// ---------------------------------------------------------------------------
// Launch
// ---------------------------------------------------------------------------
extern "C" void kernel_launch(void* const* d_in, const int* in_sizes, int n_in,
                              void* d_out, int out_size)
{
    const float* x  = (const float*)d_in[0];   // [2048,250,128]
    const float* Wi = (const float*)d_in[1];   // [128,400]
    const float* Wh = (const float*)d_in[2];   // [100,400]
    const float* bh = (const float*)d_in[3];   // [400]
    const float* Wd = (const float*)d_in[4];   // [100,100]
    const float* bd = (const float*)d_in[5];   // [100]
    float* out = (float*)d_out;                // [2048,250,100]

    const int smem1 = (64 * 128 + 80 * PWS) * 4;   // 75,008 B
    const int smem2 = 51700 * 4;                   // 206,800 B
    cudaFuncSetAttribute(gemm_xz_kernel,
                         cudaFuncAttributeMaxDynamicSharedMemorySize, smem1);
    cudaFuncSetAttribute(lstm_kernel,
                         cudaFuncAttributeMaxDynamicSharedMemorySize, smem2);

    dim3 g1(MTOT / 64, G4 / 80);   // 8000 x 5
    gemm_xz_kernel<<<g1, 256, smem1>>>(x, Wi, bh);
    lstm_kernel<<<BATCH / 16, 200, smem2>>>(Wh, Wd, bd, out);
}

// round 8
// speedup vs baseline: 1.6350x; 1.3555x over previous
#include <cuda_runtime.h>
#include <cstdint>

typedef unsigned long long ull;

#define BATCH   2048
#define TSTEPS  250
#define DIN     128
#define HID     100
#define G4      400
#define MTOT    (BATCH*TSTEPS)

// Scratch for xz : GATE-INTERLEAVED layout [m][j][g]  (index = m*400 + j*4 + g)
__device__ float g_xz[(size_t)MTOT * G4];

// ---------------------------------------------------------------------------
// helpers
// ---------------------------------------------------------------------------
__device__ __forceinline__ uint32_t sptr(const void* p) {
    return (uint32_t)__cvta_generic_to_shared(p);
}
__device__ __forceinline__ void lds2(ull& a, ull& b, uint32_t addr) {
    asm volatile("ld.shared.v2.b64 {%0,%1}, [%2];" : "=l"(a), "=l"(b) : "r"(addr));
}
__device__ __forceinline__ ull lds1(uint32_t addr) {
    ull a; asm volatile("ld.shared.b64 %0, [%1];" : "=l"(a) : "r"(addr)); return a;
}
__device__ __forceinline__ void ffma2(ull& d, ull a, ull b) {
    asm volatile("fma.rn.f32x2 %0, %1, %2, %0;" : "+l"(d) : "l"(a), "l"(b));
}
__device__ __forceinline__ ull pack2(float lo, float hi) {
    ull r; asm("mov.b64 %0, {%1,%2};" : "=l"(r) : "f"(lo), "f"(hi)); return r;
}
__device__ __forceinline__ float hsum2(ull v) {
    float lo, hi; asm("mov.b64 {%0,%1}, %2;" : "=f"(lo), "=f"(hi) : "l"(v));
    return lo + hi;
}
__device__ __forceinline__ void cpasync16(uint32_t dst, const void* src) {
    asm volatile("cp.async.ca.shared.global [%0], [%1], 16;" :: "r"(dst), "l"(src));
}
__device__ __forceinline__ void mma_tf32(float c[4], uint32_t a0, uint32_t a1,
                                         uint32_t a2, uint32_t a3,
                                         uint32_t b0, uint32_t b1) {
    asm volatile(
        "mma.sync.aligned.m16n8k8.row.col.f32.tf32.tf32.f32 "
        "{%0,%1,%2,%3}, {%4,%5,%6,%7}, {%8,%9}, {%0,%1,%2,%3};"
        : "+f"(c[0]), "+f"(c[1]), "+f"(c[2]), "+f"(c[3])
        : "r"(a0), "r"(a1), "r"(a2), "r"(a3), "r"(b0), "r"(b1));
}

// ---------------------------------------------------------------------------
// Kernel 1: xz = x@Wi + bh via tf32 mma.sync, output gate-interleaved.
// M=512000, K=128, N=400. CTA: 128 thr (4 warps), BM=64, BN=80 where the 80
// columns are {g*100 + j0 + jj : g in 0..3, jj in 0..19}  (j0 = 20*blockIdx.y).
// Epilogue stages through smem and writes coalesced float4 in [m][j][g] order.
// ---------------------------------------------------------------------------
#define BM 64
#define XS_STR 132    // x tile row stride (floats): conflict-free a-frag loads
#define WS_STR 88     // Wi tile row stride (floats): conflict-free b-frag loads
#define SO_STR 84     // staging row stride

__global__ __launch_bounds__(128) void gemm_xz_kernel(
    const float* __restrict__ x,
    const float* __restrict__ Wi,
    const float* __restrict__ bh)
{
    extern __shared__ float sm1[];
    float* xs  = sm1;                         // [64][132]
    float* ws  = sm1 + 64 * XS_STR;           // [128][88] (k-major; 80 cols used)
    float* sbh = ws + 128 * WS_STR;           // [80] bias in output-staging order
    float* sout = ws;                         // reuse ws region for epilogue stage

    const int tid = threadIdx.x;
    const int m0  = blockIdx.x * BM;
    const int j0  = blockIdx.y * 20;

    // bias in staged order: p = jj*4 + gg  ->  bh[gg*100 + j0 + jj]
    if (tid < 80) sbh[tid] = bh[(tid & 3) * 100 + j0 + (tid >> 2)];

    // x tile: 64 rows x 32 16B-chunks
    {
        const uint32_t xb = sptr(xs);
#pragma unroll
        for (int q = 0; q < 16; q++) {
            int i = tid + q * 128;
            int r = i >> 5, c = i & 31;
            cpasync16(xb + (r * XS_STR + c * 4) * 4,
                      x + (size_t)(m0 + r) * DIN + c * 4);
        }
    }
    // Wi tile: 128 k-rows x 4 gates x 5 16B-chunks; local col = gg*20 + jj
    {
        const uint32_t wb = sptr(ws);
#pragma unroll
        for (int q = 0; q < 20; q++) {
            int i = tid + q * 128;
            int k = i / 20, rem = i % 20;
            int gg = rem / 5, cc = rem % 5;
            cpasync16(wb + (k * WS_STR + gg * 20 + cc * 4) * 4,
                      Wi + (size_t)k * G4 + gg * 100 + j0 + cc * 4);
        }
    }
    asm volatile("cp.async.commit_group;");
    asm volatile("cp.async.wait_group 0;");
    __syncthreads();

    const int warp = tid >> 5, lane = tid & 31;
    const int gid = lane >> 2, tig = lane & 3;
    const int r0w = warp * 16;

    float acc[10][4];
#pragma unroll
    for (int nt = 0; nt < 10; nt++)
#pragma unroll
        for (int q = 0; q < 4; q++) acc[nt][q] = 0.f;

    const float* xa0 = xs + (r0w + gid) * XS_STR;
    const float* xa1 = xs + (r0w + gid + 8) * XS_STR;

#pragma unroll
    for (int kk = 0; kk < 16; kk++) {
        const int k0 = kk * 8;
        uint32_t a0 = __float_as_uint(xa0[k0 + tig]);
        uint32_t a1 = __float_as_uint(xa1[k0 + tig]);
        uint32_t a2 = __float_as_uint(xa0[k0 + tig + 4]);
        uint32_t a3 = __float_as_uint(xa1[k0 + tig + 4]);
        const float* w0 = ws + (k0 + tig) * WS_STR + gid;
        const float* w1 = ws + (k0 + tig + 4) * WS_STR + gid;
#pragma unroll
        for (int nt = 0; nt < 10; nt++) {
            uint32_t b0 = __float_as_uint(w0[nt * 8]);
            uint32_t b1 = __float_as_uint(w1[nt * 8]);
            mma_tf32(acc[nt], a0, a1, a2, a3, b0, b1);
        }
    }
    __syncthreads();   // done reading ws; reuse as staging

    // stage accums into sout[row][p], p = (n'%20)*4 + n'/20
    // FIX(R6): rows are r0w+gid / r0w+gid+8 (R5 omitted r0w -> inter-warp race)
#pragma unroll
    for (int nt = 0; nt < 10; nt++) {
        int n0c = nt * 8 + 2 * tig;
        int n1c = n0c + 1;
        int p0 = (n0c % 20) * 4 + n0c / 20;
        int p1 = (n1c % 20) * 4 + n1c / 20;
        sout[(r0w + gid) * SO_STR + p0]     = acc[nt][0];
        sout[(r0w + gid) * SO_STR + p1]     = acc[nt][1];
        sout[(r0w + gid + 8) * SO_STR + p0] = acc[nt][2];
        sout[(r0w + gid + 8) * SO_STR + p1] = acc[nt][3];
    }
    __syncthreads();

    // coalesced write-out: 64 rows x 20 float4 (+bias)
    float4* gout = (float4*)g_xz;
#pragma unroll
    for (int q = 0; q < 10; q++) {
        int i = tid + q * 128;
        int r = i / 20, c = i % 20;
        float4 v;
        v.x = sout[r * SO_STR + 4 * c + 0] + sbh[4 * c + 0];
        v.y = sout[r * SO_STR + 4 * c + 1] + sbh[4 * c + 1];
        v.z = sout[r * SO_STR + 4 * c + 2] + sbh[4 * c + 2];
        v.w = sout[r * SO_STR + 4 * c + 3] + sbh[4 * c + 3];
        gout[(size_t)(m0 + r) * 100 + 20 * blockIdx.y + c] = v;
    }
}

// ---------------------------------------------------------------------------
// Kernel 2: persistent LSTM recurrence + fused projection, f32x2.
// 128 CTAs x 16 rows, 200 threads: thread = (j = tid%100, rr = tid/100),
// owns 8 rows. Double-buffered h -> ONE barrier per step.
// xz gate-interleaved: one LDG.128 per (row, step) fetches all 4 gates.
// ---------------------------------------------------------------------------
__device__ __forceinline__ float sigf(float xv) {
    return __fdividef(1.f, 1.f + __expf(-xv));
}
__device__ __forceinline__ float tanh_f(float xv) {
    float e = __expf(2.f * xv);
    return 1.f - __fdividef(2.f, e + 1.f);
}

__global__ __launch_bounds__(200) void lstm_kernel(
    const float* __restrict__ Wh,
    const float* __restrict__ Wd,
    const float* __restrict__ bd,
    float* __restrict__ out)
{
    extern __shared__ float sm2[];
    float* Wq  = sm2;                 // 40000 floats
    float* Wdp = sm2 + 40000;         // 10000 floats
    float* hsm = sm2 + 50000;         // 2 x 1600 floats (double buffer)
    float* bds = sm2 + 53200;         // 100 floats

    const int tid = threadIdx.x;      // 0..199

    for (int i = tid; i < HID * G4; i += 200) {
        int k = i / G4, c = i - k * G4;
        int k2 = k >> 1, kl = k & 1;
        int g = c / HID, j = c - g * HID;
        int gp = g >> 1, gl = g & 1;
        Wq[(((k2 * 2 + gp) * HID + j) << 2) + gl * 2 + kl] = Wh[i];
    }
    for (int i = tid; i < HID * HID; i += 200) {
        int k = i / HID, j = i - k * HID;
        Wdp[(k >> 1) * (2 * HID) + j * 2 + (k & 1)] = Wd[i];
    }
    for (int i = tid; i < 16 * HID; i += 200) hsm[i] = 0.f;   // buffer 0 only
    if (tid < HID) bds[tid] = bd[tid];
    __syncthreads();

    const int j  = tid % HID;
    const int rr = tid / HID;                     // 0..1
    const int r0 = blockIdx.x * 16 + rr * 8;      // first of this thread's 8 rows

    const uint32_t hbase = sptr(hsm) + (rr * 8) * (HID * 4);
    const uint32_t wqb   = sptr(Wq)  + j * 16;
    const uint32_t wdb   = sptr(Wdp) + j * 8;

    float cst[8];
#pragma unroll
    for (int i = 0; i < 8; i++) cst[i] = 0.f;

    // prefetched xz (current step): 8 rows x float4(4 gates)
    const float4* xzg = (const float4*)g_xz;
    float4 xzn[8];
#pragma unroll
    for (int i = 0; i < 8; i++)
        xzn[i] = __ldcs(xzg + ((size_t)(r0 + i) * TSTEPS) * HID + j);

    int cur = 0;
    for (int t = 0; t < TSTEPS; t++) {
        ull acc[8][4];
#pragma unroll
        for (int i = 0; i < 8; i++) {
            acc[i][0] = pack2(xzn[i].x, 0.f);
            acc[i][1] = pack2(xzn[i].y, 0.f);
            acc[i][2] = pack2(xzn[i].z, 0.f);
            acc[i][3] = pack2(xzn[i].w, 0.f);
        }
        if (t + 1 < TSTEPS) {
#pragma unroll
            for (int i = 0; i < 8; i++)
                xzn[i] = __ldcs(xzg + ((size_t)(r0 + i) * TSTEPS + (t + 1)) * HID + j);
        }

        const uint32_t hrow = hbase + cur * 6400;
        const uint32_t hnxt = hbase + (cur ^ 1) * 6400;

        // recurrence: acc[i][g] += sum_k h[r][k] * Wh[k][g*100+j]
#pragma unroll 5
        for (int k4 = 0; k4 < 25; k4++) {
            ull a[8][2];
#pragma unroll
            for (int i = 0; i < 8; i++)
                lds2(a[i][0], a[i][1], hrow + i * (HID * 4) + k4 * 16);
            ull bg[2][4];
#pragma unroll
            for (int kl = 0; kl < 2; kl++) {
                int k2 = 2 * k4 + kl;
                lds2(bg[kl][0], bg[kl][1], wqb + (k2 * 2 + 0) * (HID * 16));
                lds2(bg[kl][2], bg[kl][3], wqb + (k2 * 2 + 1) * (HID * 16));
            }
#pragma unroll
            for (int i = 0; i < 8; i++)
#pragma unroll
                for (int g = 0; g < 4; g++) {
                    ffma2(acc[i][g], a[i][0], bg[0][g]);
                    ffma2(acc[i][g], a[i][1], bg[1][g]);
                }
        }

        // gates (i, f, g, o)
        float hnew[8];
#pragma unroll
        for (int i = 0; i < 8; i++) {
            const float ig = sigf(hsum2(acc[i][0]));
            const float fg = sigf(hsum2(acc[i][1]));
            const float gg = tanh_f(hsum2(acc[i][2]));
            const float og = sigf(hsum2(acc[i][3]));
            const float c  = fg * cst[i] + ig * gg;
            cst[i]  = c;
            hnew[i] = og * tanh_f(c);
        }

        // write new h into the OTHER buffer; single barrier
        float* hn = hsm + (cur ^ 1) * 1600;
#pragma unroll
        for (int i = 0; i < 8; i++) hn[(rr * 8 + i) * HID + j] = hnew[i];
        __syncthreads();

        // projection reads the new buffer
        ull pv[8];
#pragma unroll
        for (int i = 0; i < 8; i++) pv[i] = 0ull;
#pragma unroll 5
        for (int k4 = 0; k4 < 25; k4++) {
            ull a[8][2];
#pragma unroll
            for (int i = 0; i < 8; i++)
                lds2(a[i][0], a[i][1], hnxt + i * (HID * 4) + k4 * 16);
            const ull w0 = lds1(wdb + (2 * k4 + 0) * (HID * 8));
            const ull w1 = lds1(wdb + (2 * k4 + 1) * (HID * 8));
#pragma unroll
            for (int i = 0; i < 8; i++) {
                ffma2(pv[i], a[i][0], w0);
                ffma2(pv[i], a[i][1], w1);
            }
        }
        const float bj = bds[j];
#pragma unroll
        for (int i = 0; i < 8; i++) {
            const float v = hsum2(pv[i]) + bj;
            out[((size_t)(r0 + i) * TSTEPS + t) * HID + j] = fmaxf(v, 0.f);
        }

        cur ^= 1;
    }
}

// ---------------------------------------------------------------------------
// Launch
// ---------------------------------------------------------------------------
extern "C" void kernel_launch(void* const* d_in, const int* in_sizes, int n_in,
                              void* d_out, int out_size)
{
    const float* x  = (const float*)d_in[0];   // [2048,250,128]
    const float* Wi = (const float*)d_in[1];   // [128,400]
    const float* Wh = (const float*)d_in[2];   // [100,400]
    const float* bh = (const float*)d_in[3];   // [400]
    const float* Wd = (const float*)d_in[4];   // [100,100]
    const float* bd = (const float*)d_in[5];   // [100]
    float* out = (float*)d_out;                // [2048,250,100]

    const int smem1 = (64 * XS_STR + 128 * WS_STR + 80) * 4;   // 79,168 B
    const int smem2 = 53300 * 4;                               // 213,200 B
    cudaFuncSetAttribute(gemm_xz_kernel,
                         cudaFuncAttributeMaxDynamicSharedMemorySize, smem1);
    cudaFuncSetAttribute(lstm_kernel,
                         cudaFuncAttributeMaxDynamicSharedMemorySize, smem2);

    dim3 g1(MTOT / BM, 5);   // 8000 x 5
    gemm_xz_kernel<<<g1, 128, smem1>>>(x, Wi, bh);
    lstm_kernel<<<BATCH / 16, 200, smem2>>>(Wh, Wd, bd, out);
}